// round 10
// baseline (speedup 1.0000x reference)
#include <cuda_runtime.h>
#include <cuda_fp16.h>
#include <cstdint>

// Mean-shift as unnormalized attention, single persistent kernel (f16 path).
//   S = (sX)^T (sX), s^2 = 2*log2(e)  =>  P = ex2(S) = exp(2*x_i.x_j)
//   GEMM1 f16-accum -> S already in A-frag layout; P = ex2.f16x2 in place.
//   deg = P @ ones (tensor);  O = P @ V (tensor, fp32 accum)
// Cross-tile software pipeline: GEMM1(it+1) issues before ex2/GEMM2(it) so
// tensor work overlaps the MUFU/dependency window. 2-tile unrolled loop.

#define NPTS   9216
#define DIM    32
#define ETA    0.5f
#define SCALE  1.6986436f          // sqrt(2*log2(e))
#define TJ     64
#define TI     64
#define KSPLIT 4
#define JT     (NPTS / TJ)             // 144
#define NT     (NPTS / (TI * KSPLIT))  // 36 tiles per split (even)
#define GRID   (JT * KSPLIT)           // 576
#define FRAME  (DIM * NPTS)

#define KST 80
#define VST 144
#define ONES2 0x3C003C00u

#define KBUF 5120
#define VBUF 4608
#define SH_K 0
#define SH_V (3 * KBUF)
#define SH_X 0
#define SH_XD 8192
#define SMEM_BYTES (3 * KBUF + 3 * VBUF)   // 29184

__device__ __align__(16) __half g_s[NPTS * DIM];  // [i][d], scaled, f16
__device__ __align__(16) __half g_v[DIM * NPTS];  // [d][i], f16
__device__ float g_accum[KSPLIT][DIM][NPTS];
__device__ float g_degp[KSPLIT][NPTS];
__device__ unsigned g_bar;
__device__ unsigned g_fin;

// ---------------- helpers ----------------
__device__ __forceinline__ uint32_t smem_u32(const void* p) {
    uint32_t a;
    asm("{ .reg .u64 t; cvta.to.shared.u64 t, %1; cvt.u32.u64 %0, t; }" : "=r"(a) : "l"(p));
    return a;
}
__device__ __forceinline__ void ldsm4(uint32_t* r, uint32_t a) {
    asm volatile("ldmatrix.sync.aligned.m8n8.x4.shared.b16 {%0,%1,%2,%3}, [%4];"
        : "=r"(r[0]), "=r"(r[1]), "=r"(r[2]), "=r"(r[3]) : "r"(a));
}
__device__ __forceinline__ void mma16816(float* c, const uint32_t* a,
                                         uint32_t b0, uint32_t b1) {
    asm volatile("mma.sync.aligned.m16n8k16.row.col.f32.f16.f16.f32 "
        "{%0,%1,%2,%3}, {%4,%5,%6,%7}, {%8,%9}, {%0,%1,%2,%3};"
        : "+f"(c[0]), "+f"(c[1]), "+f"(c[2]), "+f"(c[3])
        : "r"(a[0]), "r"(a[1]), "r"(a[2]), "r"(a[3]), "r"(b0), "r"(b1));
}
__device__ __forceinline__ void mma16816h(uint32_t* c, const uint32_t* a,
                                          uint32_t b0, uint32_t b1) {
    asm volatile("mma.sync.aligned.m16n8k16.row.col.f16.f16.f16.f16 "
        "{%0,%1}, {%2,%3,%4,%5}, {%6,%7}, {%0,%1};"
        : "+r"(c[0]), "+r"(c[1])
        : "r"(a[0]), "r"(a[1]), "r"(a[2]), "r"(a[3]), "r"(b0), "r"(b1));
}
__device__ __forceinline__ uint32_t cvt_f16x2(float lo, float hi) {
    uint32_t r;
    asm("cvt.rn.f16x2.f32 %0, %1, %2;" : "=r"(r) : "f"(hi), "f"(lo));
    return r;
}
__device__ __forceinline__ uint32_t ex2_h2(uint32_t x) {
    uint32_t y;
    asm("ex2.approx.f16x2 %0, %1;" : "=r"(y) : "r"(x));
    return y;
}
#define CP16(dst, src) asm volatile("cp.async.cg.shared.global [%0], [%1], 16;" :: "r"(dst), "l"(src) : "memory")
#define CP_COMMIT()    asm volatile("cp.async.commit_group;" ::: "memory")
#define CP_WAIT0()     asm volatile("cp.async.wait_group 0;" ::: "memory")
#define CP_WAIT1()     asm volatile("cp.async.wait_group 1;" ::: "memory")

__device__ __forceinline__ void grid_bar(unsigned tgt) {
    __syncthreads();
    __threadfence();
    if (threadIdx.x == 0) {
        atomicAdd(&g_bar, 1u);
        while (*(volatile unsigned*)&g_bar < tgt) __nanosleep(32);
    }
    __syncthreads();
}

__device__ __forceinline__ void stage_tiles(uint32_t kdst, uint32_t vdst,
                                            int i0, int tid) {
    const char* ks = reinterpret_cast<const char*>(g_s) + (size_t)i0 * (DIM * 2);
#pragma unroll
    for (int v = 0; v < 2; v++) {
        int idx = v * 128 + tid, row = idx >> 2, c = idx & 3;
        CP16(kdst + row * KST + c * 16, ks + row * 64 + c * 16);
    }
    const char* vs = reinterpret_cast<const char*>(g_v) + (size_t)i0 * 2;
#pragma unroll
    for (int v = 0; v < 2; v++) {
        int idx = v * 128 + tid, row = idx >> 3, c = idx & 7;
        CP16(vdst + row * VST + c * 16, vs + (size_t)row * (NPTS * 2) + c * 16);
    }
}

// One pipelined half-step: GEMM1 for tile (cur+1) into SNXT, then
// ex2 + deg + GEMM2 for tile (cur) from SCUR. Rotates buffers bc/bn/bs.
#define HALF_STEP(cur, SCUR, SNXT)                                            \
    {                                                                          \
        if ((cur) + 1 < NT) { CP_WAIT0(); }                                    \
        __syncthreads();                                                       \
        if ((cur) + 2 < NT) {                                                  \
            stage_tiles(smbase + SH_K + bs * KBUF, smbase + SH_V + bs * VBUF,  \
                        i00 + ((cur) + 2) * TI, tid);                          \
            CP_COMMIT();                                                       \
        }                                                                      \
        if ((cur) + 1 < NT) {                                                  \
            const uint32_t kofs = (uint32_t)bn * KBUF;                         \
            _Pragma("unroll")                                                  \
            for (int x = 0; x < 16; x++) SNXT[x] = 0u;                         \
            _Pragma("unroll")                                                  \
            for (int nt = 0; nt < 4; nt++) {                                   \
                uint32_t kb[4];                                                \
                ldsm4(kb, ka0[nt] + kofs);                                     \
                mma16816h(&SNXT[nt * 2],     qa,      kb[0], kb[1]);           \
                mma16816h(&SNXT[nt * 2],     qa + 4,  kb[2], kb[3]);           \
                mma16816h(&SNXT[8 + nt * 2], qa + 8,  kb[0], kb[1]);           \
                mma16816h(&SNXT[8 + nt * 2], qa + 12, kb[2], kb[3]);           \
            }                                                                  \
        }                                                                      \
        _Pragma("unroll")                                                      \
        for (int x = 0; x < 16; x++) SCUR[x] = ex2_h2(SCUR[x]);                \
        _Pragma("unroll")                                                      \
        for (int mt = 0; mt < 2; mt++) {                                       \
            mma16816(&dacc[mt * 4], &SCUR[mt * 8],     ONES2, ONES2);          \
            mma16816(&dacc[mt * 4], &SCUR[mt * 8 + 4], ONES2, ONES2);          \
        }                                                                      \
        {                                                                      \
            const uint32_t vofs = (uint32_t)bc * VBUF;                         \
            _Pragma("unroll")                                                  \
            for (int dt = 0; dt < 4; dt++) {                                   \
                uint32_t vb[4];                                                \
                ldsm4(vb, va0[dt] + vofs);                                     \
                mma16816(&O[dt * 4],      &SCUR[0],  vb[0], vb[1]);            \
                mma16816(&O[dt * 4],      &SCUR[4],  vb[2], vb[3]);            \
                mma16816(&O[16 + dt * 4], &SCUR[8],  vb[0], vb[1]);            \
                mma16816(&O[16 + dt * 4], &SCUR[12], vb[2], vb[3]);            \
            }                                                                  \
        }                                                                      \
        { int _tmp = bc; bc = bn; bn = bs; bs = _tmp; }                        \
    }

__global__ void __launch_bounds__(128, 4)
ms_persist(const float* __restrict__ x_in, float* __restrict__ out) {
    __shared__ __align__(16) uint8_t sm[SMEM_BYTES];

    const int tid = threadIdx.x, w = tid >> 5, lane = tid & 31;
    const int wq = w >> 1, wk = w & 1;
    const int jt = blockIdx.x, split = blockIdx.y;
    const unsigned gid = (blockIdx.y * JT + blockIdx.x) * 128u + tid;
    const uint32_t smbase = smem_u32(sm);
    unsigned tgt = 0;

    // ---------------- phase 0: init (4 threads per pixel) ----------------
    if (gid < NPTS * 4u) {
        const int j = gid >> 2, d0 = (gid & 3) * 8;
        uint32_t pk[4];
#pragma unroll
        for (int q = 0; q < 4; q++) {
            int d = d0 + q * 2;
            float x0 = x_in[d * NPTS + j];
            float x1 = x_in[(d + 1) * NPTS + j];
            out[d * NPTS + j] = x0;
            out[(d + 1) * NPTS + j] = x1;
            g_v[d * NPTS + j] = __float2half(x0);
            g_v[(d + 1) * NPTS + j] = __float2half(x1);
            pk[q] = cvt_f16x2(x0 * SCALE, x1 * SCALE);
        }
        *reinterpret_cast<uint4*>(g_s + j * DIM + d0) =
            make_uint4(pk[0], pk[1], pk[2], pk[3]);
    }
    tgt += GRID; grid_bar(tgt);

    // hoisted ldsm addresses (buffer 0; add buf*KBUF / buf*VBUF)
    uint32_t ka0[4], va0[4];
#pragma unroll
    for (int nt = 0; nt < 4; nt++)
        ka0[nt] = smbase + SH_K + (wk * 32 + nt * 8 + (lane & 7)) * KST + (lane >> 3) * 16;
#pragma unroll
    for (int dt = 0; dt < 4; dt++)
        va0[dt] = smbase + SH_V + (dt * 8 + (lane & 7)) * VST + (wk * 32 + (lane >> 3) * 8) * 2;

    for (int t = 0; t < 3; t++) {
        // ---------------- attention phase ----------------
        const int j0 = jt * TJ;
        {
            const uint4* src = reinterpret_cast<const uint4*>(g_s) + j0 * 4;
#pragma unroll
            for (int v = 0; v < 2; v++) {
                int idx = v * 128 + tid, row = idx >> 2, c = idx & 3;
                uint4 val = __ldcg(&src[row * 4 + c]);
                *reinterpret_cast<uint4*>(&sm[SH_K + row * KST + c * 16]) = val;
            }
        }
        __syncthreads();
        uint32_t qa[16];
        {
            int m = lane >> 3, r = lane & 7;
#pragma unroll
            for (int mt = 0; mt < 2; mt++) {
                uint32_t base = smbase + SH_K +
                    (wq * 32 + mt * 16 + (m & 1) * 8 + r) * KST + (m >> 1) * 16;
                ldsm4(qa + mt * 8, base);
                ldsm4(qa + mt * 8 + 4, base + 32);
            }
        }
        __syncthreads();

        float O[32];
#pragma unroll
        for (int i = 0; i < 32; i++) O[i] = 0.0f;
        float dacc[8];
#pragma unroll
        for (int i = 0; i < 8; i++) dacc[i] = 0.0f;

        const int i00 = split * (NPTS / KSPLIT);
        stage_tiles(smbase + SH_K,        smbase + SH_V,        i00,      tid);
        CP_COMMIT();
        stage_tiles(smbase + SH_K + KBUF, smbase + SH_V + VBUF, i00 + TI, tid);
        CP_COMMIT();

        int bc = 0, bn = 1, bs = 2;
        uint32_t scA[16], scB[16];

        // prologue: GEMM1 for tile 0 -> scA
        CP_WAIT1();
        __syncthreads();
#pragma unroll
        for (int x = 0; x < 16; x++) scA[x] = 0u;
#pragma unroll
        for (int nt = 0; nt < 4; nt++) {
            uint32_t kb[4];
            ldsm4(kb, ka0[nt]);          // buf 0
            mma16816h(&scA[nt * 2],     qa,      kb[0], kb[1]);
            mma16816h(&scA[nt * 2],     qa + 4,  kb[2], kb[3]);
            mma16816h(&scA[8 + nt * 2], qa + 8,  kb[0], kb[1]);
            mma16816h(&scA[8 + nt * 2], qa + 12, kb[2], kb[3]);
        }

        for (int it = 0; it < NT; it += 2) {
            HALF_STEP(it,     scA, scB);
            HALF_STEP(it + 1, scB, scA);
        }

        // ---- cross-warp (wk) reduction of O and deg via smem ----
        __syncthreads();   // all warps done with K/V buffers (SH_X aliases them)
        if (wk == 1) {
#pragma unroll
            for (int r4 = 0; r4 < 8; r4++)
                *reinterpret_cast<float4*>(&sm[SH_X + wq * 4096 + r4 * 512 + lane * 16]) =
                    make_float4(O[r4 * 4], O[r4 * 4 + 1], O[r4 * 4 + 2], O[r4 * 4 + 3]);
            *reinterpret_cast<float2*>(&sm[SH_XD + wq * 512 + lane * 8]) =
                make_float2(dacc[0], dacc[2]);
            *reinterpret_cast<float2*>(&sm[SH_XD + wq * 512 + 256 + lane * 8]) =
                make_float2(dacc[4], dacc[6]);
        }
        __syncthreads();
        if (wk == 0) {
#pragma unroll
            for (int r4 = 0; r4 < 8; r4++) {
                float4 pv = *reinterpret_cast<const float4*>(
                    &sm[SH_X + wq * 4096 + r4 * 512 + lane * 16]);
                O[r4 * 4]     += pv.x;
                O[r4 * 4 + 1] += pv.y;
                O[r4 * 4 + 2] += pv.z;
                O[r4 * 4 + 3] += pv.w;
            }
            float2 p0 = *reinterpret_cast<const float2*>(&sm[SH_XD + wq * 512 + lane * 8]);
            float2 p1 = *reinterpret_cast<const float2*>(&sm[SH_XD + wq * 512 + 256 + lane * 8]);
            dacc[0] += p0.x; dacc[2] += p0.y;
            dacc[4] += p1.x; dacc[6] += p1.y;

#pragma unroll
            for (int mt = 0; mt < 2; mt++) {
                const int jj = j0 + wq * 32 + mt * 16 + (lane >> 2);
#pragma unroll
                for (int dt = 0; dt < 4; dt++) {
                    int d0 = dt * 8 + 2 * (lane & 3);
                    g_accum[split][d0][jj]         = O[mt * 16 + dt * 4 + 0];
                    g_accum[split][d0 + 1][jj]     = O[mt * 16 + dt * 4 + 1];
                    g_accum[split][d0][jj + 8]     = O[mt * 16 + dt * 4 + 2];
                    g_accum[split][d0 + 1][jj + 8] = O[mt * 16 + dt * 4 + 3];
                }
                if ((lane & 3) == 0) {
                    g_degp[split][jj]     = dacc[mt * 4 + 0];
                    g_degp[split][jj + 8] = dacc[mt * 4 + 2];
                }
            }
        }
        tgt += GRID; grid_bar(tgt);

        // ---------------- reduce phase (4 threads per pixel) ----------------
        if (gid < NPTS * 4u) {
            const int j = gid >> 2, d0 = (gid & 3) * 8;
            float deg = 0.0f;
#pragma unroll
            for (int sp = 0; sp < KSPLIT; sp++) deg += __ldcg(&g_degp[sp][j]);
            const float inv = ETA / deg;
            const float* X  = out + (size_t)t * FRAME;
            float*       Xn = out + (size_t)(t + 1) * FRAME;
            uint32_t pk[4];
#pragma unroll
            for (int q = 0; q < 4; q++) {
                int d = d0 + q * 2;
                float a0 = 0.0f, a1 = 0.0f;
#pragma unroll
                for (int sp = 0; sp < KSPLIT; sp++) {
                    a0 += __ldcg(&g_accum[sp][d][j]);
                    a1 += __ldcg(&g_accum[sp][d + 1][j]);
                }
                float x0 = a0 * inv + (1.0f - ETA) * X[d * NPTS + j];
                float x1 = a1 * inv + (1.0f - ETA) * X[(d + 1) * NPTS + j];
                Xn[d * NPTS + j] = x0;
                Xn[(d + 1) * NPTS + j] = x1;
                if (t < 2) {
                    g_v[d * NPTS + j] = __float2half(x0);
                    g_v[(d + 1) * NPTS + j] = __float2half(x1);
                    pk[q] = cvt_f16x2(x0 * SCALE, x1 * SCALE);
                }
            }
            if (t < 2)
                *reinterpret_cast<uint4*>(g_s + j * DIM + d0) =
                    make_uint4(pk[0], pk[1], pk[2], pk[3]);
        }
        if (t < 2) { tgt += GRID; grid_bar(tgt); }
    }

    // ---------------- epilogue: counter reset handshake ----------------
    __syncthreads();
    __threadfence();
    if (tid == 0) atomicAdd(&g_fin, 1u);
    if (gid == 0) {
        while (*(volatile unsigned*)&g_fin < GRID) __nanosleep(64);
        *(volatile unsigned*)&g_bar = 0;
        *(volatile unsigned*)&g_fin = 0;
        __threadfence();
    }
}

extern "C" void kernel_launch(void* const* d_in, const int* in_sizes, int n_in,
                              void* d_out, int out_size) {
    const float* x_in = (const float*)d_in[0];
    float* out = (float*)d_out;
    dim3 grid(JT, KSPLIT);
    ms_persist<<<grid, 128>>>(x_in, out);
}

// round 11
// speedup vs baseline: 1.0466x; 1.0466x over previous
#include <cuda_runtime.h>
#include <cuda_fp16.h>
#include <cstdint>

// Mean-shift as unnormalized attention, single persistent kernel (f16 path).
//   S = (sX)^T (sX), s^2 = 2*log2(e)  =>  P = ex2(S) = exp(2*x_i.x_j)
//   GEMM1 f16-accum -> S already in A-frag layout; P = ex2.f16x2 in place.
//   deg = P @ ones (tensor);  O = P @ V (tensor, fp32 accum)
// Free-running warp pairs: each wk-pair owns a private 3-stage K/V ring,
// synced by named barrier only -> NO __syncthreads in the 36-tile loop.
// CTAs/pairs drift apart, decorrelating per-SMSP MUFU ex2 bursts.

#define NPTS   9216
#define DIM    32
#define ETA    0.5f
#define SCALE  1.6986436f          // sqrt(2*log2(e))
#define TJ     64
#define TI     64
#define KSPLIT 4
#define JT     (NPTS / TJ)             // 144
#define NT     (NPTS / (TI * KSPLIT))  // 36 tiles per split
#define GRID   (JT * KSPLIT)           // 576
#define FRAME  (DIM * NPTS)

#define KST 80                  // 80B row stride: conflict-free ldmatrix
#define ONES2 0x3C003C00u

// pair ring: 3 stages x (K 32x80 + V 32x80) = 3 x 5120
#define STG  5120
#define RING (3 * STG)          // 15360 per pair
#define SMEM_BYTES (2 * RING)   // 30720
#define SH_X 0                  // O exchange (8KB), aliases pair-0 ring
#define SH_XD 8192              // deg exchange (1KB)

__device__ __align__(16) __half g_s[NPTS * DIM];  // [i][d], scaled, f16
__device__ __align__(16) __half g_v[DIM * NPTS];  // [d][i], f16
__device__ float g_accum[KSPLIT][DIM][NPTS];
__device__ float g_degp[KSPLIT][NPTS];
__device__ unsigned g_bar;
__device__ unsigned g_fin;

// ---------------- helpers ----------------
__device__ __forceinline__ uint32_t smem_u32(const void* p) {
    uint32_t a;
    asm("{ .reg .u64 t; cvta.to.shared.u64 t, %1; cvt.u32.u64 %0, t; }" : "=r"(a) : "l"(p));
    return a;
}
__device__ __forceinline__ void ldsm4(uint32_t* r, uint32_t a) {
    asm volatile("ldmatrix.sync.aligned.m8n8.x4.shared.b16 {%0,%1,%2,%3}, [%4];"
        : "=r"(r[0]), "=r"(r[1]), "=r"(r[2]), "=r"(r[3]) : "r"(a));
}
__device__ __forceinline__ void mma16816(float* c, const uint32_t* a,
                                         uint32_t b0, uint32_t b1) {
    asm volatile("mma.sync.aligned.m16n8k16.row.col.f32.f16.f16.f32 "
        "{%0,%1,%2,%3}, {%4,%5,%6,%7}, {%8,%9}, {%0,%1,%2,%3};"
        : "+f"(c[0]), "+f"(c[1]), "+f"(c[2]), "+f"(c[3])
        : "r"(a[0]), "r"(a[1]), "r"(a[2]), "r"(a[3]), "r"(b0), "r"(b1));
}
__device__ __forceinline__ void mma16816h(uint32_t* c, const uint32_t* a,
                                          uint32_t b0, uint32_t b1) {
    asm volatile("mma.sync.aligned.m16n8k16.row.col.f16.f16.f16.f16 "
        "{%0,%1}, {%2,%3,%4,%5}, {%6,%7}, {%0,%1};"
        : "+r"(c[0]), "+r"(c[1])
        : "r"(a[0]), "r"(a[1]), "r"(a[2]), "r"(a[3]), "r"(b0), "r"(b1));
}
__device__ __forceinline__ uint32_t cvt_f16x2(float lo, float hi) {
    uint32_t r;
    asm("cvt.rn.f16x2.f32 %0, %1, %2;" : "=r"(r) : "f"(hi), "f"(lo));
    return r;
}
__device__ __forceinline__ uint32_t ex2_h2(uint32_t x) {
    uint32_t y;
    asm("ex2.approx.f16x2 %0, %1;" : "=r"(y) : "r"(x));
    return y;
}
#define CP16(dst, src) asm volatile("cp.async.cg.shared.global [%0], [%1], 16;" :: "r"(dst), "l"(src) : "memory")
#define CP_COMMIT()    asm volatile("cp.async.commit_group;" ::: "memory")
#define CP_WAIT0()     asm volatile("cp.async.wait_group 0;" ::: "memory")
#define CP_WAIT1()     asm volatile("cp.async.wait_group 1;" ::: "memory")
#define BAR_PAIR(wk)   asm volatile("bar.sync %0, 64;" :: "r"(1 + (wk)) : "memory")

__device__ __forceinline__ void grid_bar(unsigned tgt) {
    __syncthreads();
    __threadfence();
    if (threadIdx.x == 0) {
        atomicAdd(&g_bar, 1u);
        while (*(volatile unsigned*)&g_bar < tgt) __nanosleep(32);
    }
    __syncthreads();
}

// Stage one 32-key K/V slice (pair-cooperative, 64 threads, 4 CP16 each).
// dst: pair ring stage base.  i0w: first key of this pair's slice.
__device__ __forceinline__ void stage_pair(uint32_t dst, int i0w, int ptid) {
    const char* gk = reinterpret_cast<const char*>(g_s) + (size_t)i0w * (DIM * 2);
#pragma unroll
    for (int cc = 0; cc < 2; cc++) {
        int idx = cc * 64 + ptid, row = idx >> 2, c = idx & 3;
        CP16(dst + row * KST + c * 16, gk + row * 64 + c * 16);
    }
    const char* gv = reinterpret_cast<const char*>(g_v) + (size_t)i0w * 2;
#pragma unroll
    for (int cc = 0; cc < 2; cc++) {
        int idx = cc * 64 + ptid, d = idx >> 2, c = idx & 3;
        CP16(dst + 2560 + d * KST + c * 16, gv + (size_t)d * (NPTS * 2) + c * 16);
    }
}

__global__ void __launch_bounds__(128, 4)
ms_persist(const float* __restrict__ x_in, float* __restrict__ out) {
    __shared__ __align__(16) uint8_t sm[SMEM_BYTES];

    const int tid = threadIdx.x, w = tid >> 5, lane = tid & 31;
    const int wq = w >> 1, wk = w & 1;
    const int ptid = wq * 32 + lane;      // pair-local thread id (0..63)
    const int jt = blockIdx.x, split = blockIdx.y;
    const unsigned gid = (blockIdx.y * JT + blockIdx.x) * 128u + tid;
    const uint32_t smbase = smem_u32(sm);
    const uint32_t rb = smbase + (uint32_t)wk * RING;   // pair ring base
    unsigned tgt = 0;

    // ---------------- phase 0: init (4 threads per pixel) ----------------
    if (gid < NPTS * 4u) {
        const int j = gid >> 2, d0 = (gid & 3) * 8;
        uint32_t pk[4];
#pragma unroll
        for (int q = 0; q < 4; q++) {
            int d = d0 + q * 2;
            float x0 = x_in[d * NPTS + j];
            float x1 = x_in[(d + 1) * NPTS + j];
            out[d * NPTS + j] = x0;
            out[(d + 1) * NPTS + j] = x1;
            g_v[d * NPTS + j] = __float2half(x0);
            g_v[(d + 1) * NPTS + j] = __float2half(x1);
            pk[q] = cvt_f16x2(x0 * SCALE, x1 * SCALE);
        }
        *reinterpret_cast<uint4*>(g_s + j * DIM + d0) =
            make_uint4(pk[0], pk[1], pk[2], pk[3]);
    }
    tgt += GRID; grid_bar(tgt);

    // hoisted ldsm addresses within a ring stage (add bc*STG per tile)
    uint32_t ka0[4], va0[4];
#pragma unroll
    for (int nt = 0; nt < 4; nt++)
        ka0[nt] = rb + (nt * 8 + (lane & 7)) * KST + (lane >> 3) * 16;
#pragma unroll
    for (int dt = 0; dt < 4; dt++)
        va0[dt] = rb + 2560 + (dt * 8 + (lane & 7)) * KST + (lane >> 3) * 16;

    for (int t = 0; t < 3; t++) {
        // ---------------- attention phase ----------------
        const int j0 = jt * TJ;
        // stage Q tile (64 x 32 f16) block-cooperatively at smem offset 0
        {
            const uint4* src = reinterpret_cast<const uint4*>(g_s) + j0 * 4;
#pragma unroll
            for (int v = 0; v < 2; v++) {
                int idx = v * 128 + tid, row = idx >> 2, c = idx & 3;
                uint4 val = __ldcg(&src[row * 4 + c]);
                *reinterpret_cast<uint4*>(&sm[row * KST + c * 16]) = val;
            }
        }
        __syncthreads();
        uint32_t qa[16];
        {
            int m = lane >> 3, r = lane & 7;
#pragma unroll
            for (int mt = 0; mt < 2; mt++) {
                uint32_t base = smbase +
                    (wq * 32 + mt * 16 + (m & 1) * 8 + r) * KST + (m >> 1) * 16;
                ldsm4(qa + mt * 8, base);
                ldsm4(qa + mt * 8 + 4, base + 32);
            }
        }
        __syncthreads();   // Q reads done before rings are overwritten

        float O[32];
#pragma unroll
        for (int i = 0; i < 32; i++) O[i] = 0.0f;
        float dacc[8];
#pragma unroll
        for (int i = 0; i < 8; i++) dacc[i] = 0.0f;

        const int i00 = split * (NPTS / KSPLIT) + wk * 32;  // this pair's slice
        stage_pair(rb,       i00,      ptid); CP_COMMIT();
        stage_pair(rb + STG, i00 + TI, ptid); CP_COMMIT();

        int bc = 0;   // current stage; target stage = (bc+2)%3
        for (int it = 0; it < NT; it++) {
            if (it + 1 < NT) { CP_WAIT1(); } else { CP_WAIT0(); }
            BAR_PAIR(wk);                 // partner's half also complete
            const uint32_t ofs = (uint32_t)bc * STG;

            // GEMM1 (f16 accum): S[2 x 16 rows][32 keys] = Q x K^T
            uint32_t sc[16];
#pragma unroll
            for (int x = 0; x < 16; x++) sc[x] = 0u;
#pragma unroll
            for (int nt = 0; nt < 4; nt++) {
                uint32_t kb[4];
                ldsm4(kb, ka0[nt] + ofs);
                mma16816h(&sc[nt * 2],     qa,      kb[0], kb[1]);
                mma16816h(&sc[nt * 2],     qa + 4,  kb[2], kb[3]);
                mma16816h(&sc[8 + nt * 2], qa + 8,  kb[0], kb[1]);
                mma16816h(&sc[8 + nt * 2], qa + 12, kb[2], kb[3]);
            }

            // P = ex2(S) in place -> GEMM2 A-fragments
#pragma unroll
            for (int x = 0; x < 16; x++) sc[x] = ex2_h2(sc[x]);

            // deg += P @ ones (tensor, fp32, deterministic)
#pragma unroll
            for (int mt = 0; mt < 2; mt++) {
                mma16816(&dacc[mt * 4], &sc[mt * 8],     ONES2, ONES2);
                mma16816(&dacc[mt * 4], &sc[mt * 8 + 4], ONES2, ONES2);
            }

            // GEMM2: O[2 x 16 rows][32 d] += P x V
#pragma unroll
            for (int dt = 0; dt < 4; dt++) {
                uint32_t vb[4];
                ldsm4(vb, va0[dt] + ofs);
                mma16816(&O[dt * 4],      &sc[0],  vb[0], vb[1]);
                mma16816(&O[dt * 4],      &sc[4],  vb[2], vb[3]);
                mma16816(&O[16 + dt * 4], &sc[8],  vb[0], vb[1]);
                mma16816(&O[16 + dt * 4], &sc[12], vb[2], vb[3]);
            }

            // prefetch tile it+2 into stage (it+2)%3 (WAR-safe: partner is
            // at >= process(it) after the barrier, reading stage it%3)
            if (it + 2 < NT) {
                int bt = bc + 2; if (bt >= 3) bt -= 3;
                stage_pair(rb + (uint32_t)bt * STG, i00 + (it + 2) * TI, ptid);
                CP_COMMIT();
            }
            bc++; if (bc == 3) bc = 0;
        }

        // ---- cross-warp (wk) reduction of O and deg via smem ----
        __syncthreads();   // all warps done with rings (SH_X aliases them)
        if (wk == 1) {
#pragma unroll
            for (int r4 = 0; r4 < 8; r4++)
                *reinterpret_cast<float4*>(&sm[SH_X + wq * 4096 + r4 * 512 + lane * 16]) =
                    make_float4(O[r4 * 4], O[r4 * 4 + 1], O[r4 * 4 + 2], O[r4 * 4 + 3]);
            *reinterpret_cast<float2*>(&sm[SH_XD + wq * 512 + lane * 8]) =
                make_float2(dacc[0], dacc[2]);
            *reinterpret_cast<float2*>(&sm[SH_XD + wq * 512 + 256 + lane * 8]) =
                make_float2(dacc[4], dacc[6]);
        }
        __syncthreads();
        if (wk == 0) {
#pragma unroll
            for (int r4 = 0; r4 < 8; r4++) {
                float4 pv = *reinterpret_cast<const float4*>(
                    &sm[SH_X + wq * 4096 + r4 * 512 + lane * 16]);
                O[r4 * 4]     += pv.x;
                O[r4 * 4 + 1] += pv.y;
                O[r4 * 4 + 2] += pv.z;
                O[r4 * 4 + 3] += pv.w;
            }
            float2 p0 = *reinterpret_cast<const float2*>(&sm[SH_XD + wq * 512 + lane * 8]);
            float2 p1 = *reinterpret_cast<const float2*>(&sm[SH_XD + wq * 512 + 256 + lane * 8]);
            dacc[0] += p0.x; dacc[2] += p0.y;
            dacc[4] += p1.x; dacc[6] += p1.y;

#pragma unroll
            for (int mt = 0; mt < 2; mt++) {
                const int jj = j0 + wq * 32 + mt * 16 + (lane >> 2);
#pragma unroll
                for (int dt = 0; dt < 4; dt++) {
                    int d0 = dt * 8 + 2 * (lane & 3);
                    g_accum[split][d0][jj]         = O[mt * 16 + dt * 4 + 0];
                    g_accum[split][d0 + 1][jj]     = O[mt * 16 + dt * 4 + 1];
                    g_accum[split][d0][jj + 8]     = O[mt * 16 + dt * 4 + 2];
                    g_accum[split][d0 + 1][jj + 8] = O[mt * 16 + dt * 4 + 3];
                }
                if ((lane & 3) == 0) {
                    g_degp[split][jj]     = dacc[mt * 4 + 0];
                    g_degp[split][jj + 8] = dacc[mt * 4 + 2];
                }
            }
        }
        tgt += GRID; grid_bar(tgt);

        // ---------------- reduce phase (4 threads per pixel) ----------------
        if (gid < NPTS * 4u) {
            const int j = gid >> 2, d0 = (gid & 3) * 8;
            float deg = 0.0f;
#pragma unroll
            for (int sp = 0; sp < KSPLIT; sp++) deg += __ldcg(&g_degp[sp][j]);
            const float inv = ETA / deg;
            const float* X  = out + (size_t)t * FRAME;
            float*       Xn = out + (size_t)(t + 1) * FRAME;
            uint32_t pk[4];
#pragma unroll
            for (int q = 0; q < 4; q++) {
                int d = d0 + q * 2;
                float a0 = 0.0f, a1 = 0.0f;
#pragma unroll
                for (int sp = 0; sp < KSPLIT; sp++) {
                    a0 += __ldcg(&g_accum[sp][d][j]);
                    a1 += __ldcg(&g_accum[sp][d + 1][j]);
                }
                float x0 = a0 * inv + (1.0f - ETA) * X[d * NPTS + j];
                float x1 = a1 * inv + (1.0f - ETA) * X[(d + 1) * NPTS + j];
                Xn[d * NPTS + j] = x0;
                Xn[(d + 1) * NPTS + j] = x1;
                if (t < 2) {
                    g_v[d * NPTS + j] = __float2half(x0);
                    g_v[(d + 1) * NPTS + j] = __float2half(x1);
                    pk[q] = cvt_f16x2(x0 * SCALE, x1 * SCALE);
                }
            }
            if (t < 2)
                *reinterpret_cast<uint4*>(g_s + j * DIM + d0) =
                    make_uint4(pk[0], pk[1], pk[2], pk[3]);
        }
        if (t < 2) { tgt += GRID; grid_bar(tgt); }
    }

    // ---------------- epilogue: counter reset handshake ----------------
    __syncthreads();
    __threadfence();
    if (tid == 0) atomicAdd(&g_fin, 1u);
    if (gid == 0) {
        while (*(volatile unsigned*)&g_fin < GRID) __nanosleep(64);
        *(volatile unsigned*)&g_bar = 0;
        *(volatile unsigned*)&g_fin = 0;
        __threadfence();
    }
}

extern "C" void kernel_launch(void* const* d_in, const int* in_sizes, int n_in,
                              void* d_out, int out_size) {
    const float* x_in = (const float*)d_in[0];
    float* out = (float*)d_out;
    dim3 grid(JT, KSPLIT);
    ms_persist<<<grid, 128>>>(x_in, out);
}